// round 10
// baseline (speedup 1.0000x reference)
#include <cuda_runtime.h>
#include <cuda_fp16.h>

#define N_NODES 100000
#define N_EDGES 1600000
#define F 64
#define SCAN_BLK 512
#define NB ((N_NODES + SCAN_BLK - 1) / SCAN_BLK)   // 196

// Scratch (device globals — zero-initialized at load; no allocation in kernel_launch)
__device__ int    g_cnt[N_NODES];        // zeroed by k_finalize after each use
__device__ int    g_scan[N_NODES];
__device__ int    g_bsum[NB];
__device__ int    g_rowptr[N_NODES + 1];
__device__ int    g_cursor[N_NODES];
__device__ int2   g_sw[N_EDGES];         // (src, bitcast dinv[src]) bucketed by dst
__device__ float  g_dinv[N_NODES];
__device__ __half g_xwh[N_NODES * F];    // x @ W, fp16

// count in-degree (real edges only); 4 edges/thread via int4
__global__ void k_count(const int* __restrict__ ei) {
    int t = blockIdx.x * blockDim.x + threadIdx.x;
    if (t < N_EDGES / 4) {
        int4 d4 = ((const int4*)(ei + N_EDGES))[t];
        if ((unsigned)d4.x < N_NODES) atomicAdd(&g_cnt[d4.x], 1);
        if ((unsigned)d4.y < N_NODES) atomicAdd(&g_cnt[d4.y], 1);
        if ((unsigned)d4.z < N_NODES) atomicAdd(&g_cnt[d4.z], 1);
        if ((unsigned)d4.w < N_NODES) atomicAdd(&g_cnt[d4.w], 1);
    }
}

// per-block inclusive scan of g_cnt
__global__ void __launch_bounds__(SCAN_BLK) k_scan_block() {
    __shared__ int s[SCAN_BLK];
    int t = threadIdx.x;
    int i = blockIdx.x * SCAN_BLK + t;
    s[t] = (i < N_NODES) ? g_cnt[i] : 0;
    __syncthreads();
    #pragma unroll
    for (int off = 1; off < SCAN_BLK; off <<= 1) {
        int v = (t >= off) ? s[t - off] : 0;
        __syncthreads();
        s[t] += v;
        __syncthreads();
    }
    if (i < N_NODES) g_scan[i] = s[t];
    if (t == SCAN_BLK - 1) g_bsum[blockIdx.x] = s[t];
}

// finalize: per-block cross-block prefix from g_bsum (warp-reduced),
// then rowptr/cursor/dinv; resets g_cnt for the next graph replay.
__global__ void __launch_bounds__(SCAN_BLK) k_finalize() {
    __shared__ int base_sh;
    int b = blockIdx.x;
    int t = threadIdx.x;
    if (t < 32) {
        int s = 0;
        for (int j = t; j < b; j += 32) s += g_bsum[j];
        #pragma unroll
        for (int o = 16; o; o >>= 1) s += __shfl_xor_sync(0xffffffffu, s, o);
        if (t == 0) base_sh = s;
    }
    __syncthreads();
    int i = b * SCAN_BLK + t;
    if (i < N_NODES) {
        int incl = g_scan[i] + base_sh;
        int cnt = g_cnt[i];
        g_cnt[i] = 0;                              // restore invariant for replay
        int excl = incl - cnt;
        g_rowptr[i] = excl;
        g_cursor[i] = excl;
        if (i == N_NODES - 1) g_rowptr[N_NODES] = incl;
        g_dinv[i] = rsqrtf((float)(cnt + 1));      // +1 self-loop
    }
}

// bucket (src, dinv[src]) by dst; 4 edges/thread via int4 on both streams
__global__ void k_fill(const int* __restrict__ ei) {
    int t = blockIdx.x * blockDim.x + threadIdx.x;
    if (t < N_EDGES / 4) {
        int4 s4 = ((const int4*)ei)[t];
        int4 d4 = ((const int4*)(ei + N_EDGES))[t];
        if ((unsigned)s4.x < N_NODES && (unsigned)d4.x < N_NODES)
            g_sw[atomicAdd(&g_cursor[d4.x], 1)] =
                make_int2(s4.x, __float_as_int(__ldg(g_dinv + s4.x)));
        if ((unsigned)s4.y < N_NODES && (unsigned)d4.y < N_NODES)
            g_sw[atomicAdd(&g_cursor[d4.y], 1)] =
                make_int2(s4.y, __float_as_int(__ldg(g_dinv + s4.y)));
        if ((unsigned)s4.z < N_NODES && (unsigned)d4.z < N_NODES)
            g_sw[atomicAdd(&g_cursor[d4.z], 1)] =
                make_int2(s4.z, __float_as_int(__ldg(g_dinv + s4.z)));
        if ((unsigned)s4.w < N_NODES && (unsigned)d4.w < N_NODES)
            g_sw[atomicAdd(&g_cursor[d4.w], 1)] =
                make_int2(s4.w, __float_as_int(__ldg(g_dinv + s4.w)));
    }
}

// GEMM: 2 adjacent cols/thread (8 FFMA per LDS.128 — halves smem-pipe load),
// K split in 2 halves so W regs stay at 64. fp16 half2 coalesced store.
#define ROWS_BLK 32
__global__ void __launch_bounds__(256) k_gemm(const float* __restrict__ x,
                                              const float* __restrict__ W) {
    __shared__ float4 xsh[ROWS_BLK * 16];
    int tid = threadIdx.x;
    int c0 = (tid & 31) * 2;            // cols c0, c0+1
    int rg = tid >> 5;                  // 0..7 row-groups of 4 rows

    int row0 = blockIdx.x * ROWS_BLK;
    const float4* x4 = (const float4*)(x + row0 * F);
    #pragma unroll
    for (int i = tid; i < ROWS_BLK * 16; i += 256) xsh[i] = x4[i];
    __syncthreads();

    float acc0[4] = {0.f, 0.f, 0.f, 0.f};
    float acc1[4] = {0.f, 0.f, 0.f, 0.f};

    #pragma unroll 1
    for (int h = 0; h < 2; h++) {
        float Wa[32], Wb[32];
        #pragma unroll
        for (int k = 0; k < 32; k++) {
            Wa[k] = W[(h * 32 + k) * F + c0];
            Wb[k] = W[(h * 32 + k) * F + c0 + 1];
        }
        #pragma unroll
        for (int rr = 0; rr < 4; rr++) {
            int r = rg * 4 + rr;
            float s0 = 0.f, s1 = 0.f;
            #pragma unroll
            for (int k0 = 0; k0 < 8; k0++) {
                float4 xv = xsh[r * 16 + h * 8 + k0];   // broadcast within warp
                s0 += xv.x * Wa[4 * k0 + 0] + xv.y * Wa[4 * k0 + 1]
                    + xv.z * Wa[4 * k0 + 2] + xv.w * Wa[4 * k0 + 3];
                s1 += xv.x * Wb[4 * k0 + 0] + xv.y * Wb[4 * k0 + 1]
                    + xv.z * Wb[4 * k0 + 2] + xv.w * Wb[4 * k0 + 3];
            }
            acc0[rr] += s0; acc1[rr] += s1;
        }
    }

    __half2* xw2 = (__half2*)g_xwh;
    #pragma unroll
    for (int rr = 0; rr < 4; rr++) {
        int row = row0 + rg * 4 + rr;
        xw2[row * 32 + (tid & 31)] = __floats2half2_rn(acc0[rr], acc1[rr]);
    }
}

// One warp per dst: 8 lanes/edge, 4 edges/warp-step. LDG.128 gathers a 16B
// slice of the fp16 row; no shfl in the loop; butterfly combine at the end.
__global__ void __launch_bounds__(256) k_accum(float* __restrict__ out,
                                               const float* __restrict__ b,
                                               const float* __restrict__ a) {
    int d = (blockIdx.x * blockDim.x + threadIdx.x) >> 5;
    int lane = threadIdx.x & 31;
    if (d >= N_NODES) return;
    int beg = g_rowptr[d];
    int end = g_rowptr[d + 1];
    float dd = g_dinv[d];
    int sl  = lane & 7;     // 16B slice of the row (8 cols)
    int grp = lane >> 3;    // 0..3: which edge of the 4-edge step

    const float4* xw4 = (const float4*)g_xwh;   // row = 8 float4 (128 B)
    float2 acc[4] = {{0.f,0.f},{0.f,0.f},{0.f,0.f},{0.f,0.f}};

    // self-loop (group 0 only, so butterfly counts it once)
    if (grp == 0) {
        float4 hv = xw4[d * 8 + sl];
        const __half2* h = (const __half2*)&hv;
        #pragma unroll
        for (int j = 0; j < 4; j++) {
            float2 v = __half22float2(h[j]);
            acc[j].x += v.x * dd; acc[j].y += v.y * dd;
        }
    }

    #pragma unroll 2
    for (int i = beg + grp; i < end; i += 4) {
        int2 p = __ldg(g_sw + i);
        float w = __int_as_float(p.y);
        float4 hv = __ldg(xw4 + p.x * 8 + sl);
        const __half2* h = (const __half2*)&hv;
        #pragma unroll
        for (int j = 0; j < 4; j++) {
            float2 v = __half22float2(h[j]);
            acc[j].x += v.x * w; acc[j].y += v.y * w;
        }
    }

    // combine the 4 groups (sl invariant under xor 8/16)
    #pragma unroll
    for (int j = 0; j < 4; j++) {
        #pragma unroll
        for (int off = 8; off <= 16; off <<= 1) {
            acc[j].x += __shfl_xor_sync(0xffffffffu, acc[j].x, off);
            acc[j].y += __shfl_xor_sync(0xffffffffu, acc[j].y, off);
        }
    }

    if (grp == 0) {
        const float4* b4 = (const float4*)b;
        float slope = a[0];
        float4* o4 = (float4*)(out + d * F);
        #pragma unroll
        for (int half4 = 0; half4 < 2; half4++) {
            float4 bb = b4[sl * 2 + half4];
            float2 a0 = acc[half4 * 2 + 0];
            float2 a1 = acc[half4 * 2 + 1];
            float4 r;
            r.x = a0.x * dd + bb.x;
            r.y = a0.y * dd + bb.y;
            r.z = a1.x * dd + bb.z;
            r.w = a1.y * dd + bb.w;
            r.x = (r.x >= 0.f) ? r.x : slope * r.x;
            r.y = (r.y >= 0.f) ? r.y : slope * r.y;
            r.z = (r.z >= 0.f) ? r.z : slope * r.z;
            r.w = (r.w >= 0.f) ? r.w : slope * r.w;
            o4[sl * 2 + half4] = r;
        }
    }
}

extern "C" void kernel_launch(void* const* d_in, const int* in_sizes, int n_in,
                              void* d_out, int out_size) {
    const float* x  = (const float*)d_in[0];
    const int*   ei = (const int*)d_in[1];   // edge_index [2, E] (int32)
    const float* W  = (const float*)d_in[2];
    const float* b  = (const float*)d_in[3];
    const float* a  = (const float*)d_in[4];
    float* out = (float*)d_out;

    k_count<<<(N_EDGES / 4 + 255) / 256, 256>>>(ei);
    k_scan_block<<<NB, SCAN_BLK>>>();
    k_finalize<<<NB, SCAN_BLK>>>();
    k_fill<<<(N_EDGES / 4 + 255) / 256, 256>>>(ei);
    k_gemm<<<N_NODES / ROWS_BLK, 256>>>(x, W);
    k_accum<<<(N_NODES * 32 + 255) / 256, 256>>>(out, b, a);
}

// round 11
// speedup vs baseline: 1.0336x; 1.0336x over previous
#include <cuda_runtime.h>
#include <cuda_fp16.h>

#define N_NODES 100000
#define N_EDGES 1600000
#define F 64
#define SCAN_BLK 512
#define NB ((N_NODES + SCAN_BLK - 1) / SCAN_BLK)   // 196

// Scratch (device globals — zero-initialized at load; no allocation in kernel_launch)
__device__ int    g_cnt[N_NODES];        // zeroed by k_finalize after each use
__device__ int    g_scan[N_NODES];
__device__ int    g_bsum[NB];
__device__ int    g_rowptr[N_NODES + 1];
__device__ int    g_cursor[N_NODES];
__device__ int    g_src[N_EDGES];        // src indices bucketed by dst
__device__ float  g_dinv[N_NODES];
__device__ __half g_xsh[N_NODES * F];    // (x @ W) * dinv[row], fp16

// count in-degree (real edges only); 4 edges/thread via int4
__global__ void k_count(const int* __restrict__ ei) {
    int t = blockIdx.x * blockDim.x + threadIdx.x;
    if (t < N_EDGES / 4) {
        int4 d4 = ((const int4*)(ei + N_EDGES))[t];
        if ((unsigned)d4.x < N_NODES) atomicAdd(&g_cnt[d4.x], 1);
        if ((unsigned)d4.y < N_NODES) atomicAdd(&g_cnt[d4.y], 1);
        if ((unsigned)d4.z < N_NODES) atomicAdd(&g_cnt[d4.z], 1);
        if ((unsigned)d4.w < N_NODES) atomicAdd(&g_cnt[d4.w], 1);
    }
}

// per-block inclusive scan of g_cnt
__global__ void __launch_bounds__(SCAN_BLK) k_scan_block() {
    __shared__ int s[SCAN_BLK];
    int t = threadIdx.x;
    int i = blockIdx.x * SCAN_BLK + t;
    s[t] = (i < N_NODES) ? g_cnt[i] : 0;
    __syncthreads();
    #pragma unroll
    for (int off = 1; off < SCAN_BLK; off <<= 1) {
        int v = (t >= off) ? s[t - off] : 0;
        __syncthreads();
        s[t] += v;
        __syncthreads();
    }
    if (i < N_NODES) g_scan[i] = s[t];
    if (t == SCAN_BLK - 1) g_bsum[blockIdx.x] = s[t];
}

// finalize: per-block cross-block prefix from g_bsum (warp-reduced),
// then rowptr/cursor/dinv; resets g_cnt for the next graph replay.
__global__ void __launch_bounds__(SCAN_BLK) k_finalize() {
    __shared__ int base_sh;
    int b = blockIdx.x;
    int t = threadIdx.x;
    if (t < 32) {
        int s = 0;
        for (int j = t; j < b; j += 32) s += g_bsum[j];
        #pragma unroll
        for (int o = 16; o; o >>= 1) s += __shfl_xor_sync(0xffffffffu, s, o);
        if (t == 0) base_sh = s;
    }
    __syncthreads();
    int i = b * SCAN_BLK + t;
    if (i < N_NODES) {
        int incl = g_scan[i] + base_sh;
        int cnt = g_cnt[i];
        g_cnt[i] = 0;                              // restore invariant for replay
        int excl = incl - cnt;
        g_rowptr[i] = excl;
        g_cursor[i] = excl;
        if (i == N_NODES - 1) g_rowptr[N_NODES] = incl;
        g_dinv[i] = rsqrtf((float)(cnt + 1));      // +1 self-loop
    }
}

// bucket src indices by dst; 4 edges/thread, int-only stores (no gathers)
__global__ void k_fill(const int* __restrict__ ei) {
    int t = blockIdx.x * blockDim.x + threadIdx.x;
    if (t < N_EDGES / 4) {
        int4 s4 = ((const int4*)ei)[t];
        int4 d4 = ((const int4*)(ei + N_EDGES))[t];
        if ((unsigned)s4.x < N_NODES && (unsigned)d4.x < N_NODES)
            g_src[atomicAdd(&g_cursor[d4.x], 1)] = s4.x;
        if ((unsigned)s4.y < N_NODES && (unsigned)d4.y < N_NODES)
            g_src[atomicAdd(&g_cursor[d4.y], 1)] = s4.y;
        if ((unsigned)s4.z < N_NODES && (unsigned)d4.z < N_NODES)
            g_src[atomicAdd(&g_cursor[d4.z], 1)] = s4.z;
        if ((unsigned)s4.w < N_NODES && (unsigned)d4.w < N_NODES)
            g_src[atomicAdd(&g_cursor[d4.w], 1)] = s4.w;
    }
}

// GEMM: 2 adjacent cols/thread (8 FFMA per LDS.128), K split in 2 halves.
// Epilogue folds dinv[row]: xs = (x@W) * dinv[row], fp16 half2 store.
#define ROWS_BLK 32
__global__ void __launch_bounds__(256) k_gemm(const float* __restrict__ x,
                                              const float* __restrict__ W) {
    __shared__ float4 xsh[ROWS_BLK * 16];
    int tid = threadIdx.x;
    int c0 = (tid & 31) * 2;            // cols c0, c0+1
    int rg = tid >> 5;                  // 0..7 row-groups of 4 rows

    int row0 = blockIdx.x * ROWS_BLK;
    const float4* x4 = (const float4*)(x + row0 * F);
    #pragma unroll
    for (int i = tid; i < ROWS_BLK * 16; i += 256) xsh[i] = x4[i];
    __syncthreads();

    float acc0[4] = {0.f, 0.f, 0.f, 0.f};
    float acc1[4] = {0.f, 0.f, 0.f, 0.f};

    #pragma unroll 1
    for (int h = 0; h < 2; h++) {
        float Wa[32], Wb[32];
        #pragma unroll
        for (int k = 0; k < 32; k++) {
            Wa[k] = W[(h * 32 + k) * F + c0];
            Wb[k] = W[(h * 32 + k) * F + c0 + 1];
        }
        #pragma unroll
        for (int rr = 0; rr < 4; rr++) {
            int r = rg * 4 + rr;
            float s0 = 0.f, s1 = 0.f;
            #pragma unroll
            for (int k0 = 0; k0 < 8; k0++) {
                float4 xv = xsh[r * 16 + h * 8 + k0];   // broadcast within warp
                s0 += xv.x * Wa[4 * k0 + 0] + xv.y * Wa[4 * k0 + 1]
                    + xv.z * Wa[4 * k0 + 2] + xv.w * Wa[4 * k0 + 3];
                s1 += xv.x * Wb[4 * k0 + 0] + xv.y * Wb[4 * k0 + 1]
                    + xv.z * Wb[4 * k0 + 2] + xv.w * Wb[4 * k0 + 3];
            }
            acc0[rr] += s0; acc1[rr] += s1;
        }
    }

    __half2* xs2 = (__half2*)g_xsh;
    #pragma unroll
    for (int rr = 0; rr < 4; rr++) {
        int row = row0 + rg * 4 + rr;
        float di = g_dinv[row];
        xs2[row * 32 + (tid & 31)] = __floats2half2_rn(acc0[rr] * di, acc1[rr] * di);
    }
}

// One warp per dst: 8 lanes/edge, 4 edges/warp-step, unit edge weight.
// Per 4 edges: 4 broadcast LDG.32 (src) + 4 LDG.128 gathers. Butterfly at end.
__global__ void __launch_bounds__(256) k_accum(float* __restrict__ out,
                                               const float* __restrict__ b,
                                               const float* __restrict__ a) {
    int d = (blockIdx.x * blockDim.x + threadIdx.x) >> 5;
    int lane = threadIdx.x & 31;
    if (d >= N_NODES) return;
    int beg = g_rowptr[d];
    int end = g_rowptr[d + 1];
    float dd = g_dinv[d];
    int sl  = lane & 7;     // 16B slice of the row (8 cols)
    int grp = lane >> 3;    // 0..3: which edge of the 4-edge step

    const float4* xs4 = (const float4*)g_xsh;   // row = 8 float4 (128 B)
    float2 acc[4] = {{0.f,0.f},{0.f,0.f},{0.f,0.f},{0.f,0.f}};

    // self-loop (group 0 only, so butterfly counts it once): xs[d] contributes
    // xs[d]*dd = xw[d]*dinv[d]^2 after the final scale.
    if (grp == 0) {
        float4 hv = xs4[d * 8 + sl];
        const __half2* h = (const __half2*)&hv;
        #pragma unroll
        for (int j = 0; j < 4; j++) {
            float2 v = __half22float2(h[j]);
            acc[j].x += v.x; acc[j].y += v.y;
        }
    }

    #pragma unroll 2
    for (int i = beg + grp; i < end; i += 4) {
        int s = __ldg(g_src + i);               // uniform within the 8-lane group
        float4 hv = __ldg(xs4 + s * 8 + sl);
        const __half2* h = (const __half2*)&hv;
        #pragma unroll
        for (int j = 0; j < 4; j++) {
            float2 v = __half22float2(h[j]);
            acc[j].x += v.x; acc[j].y += v.y;
        }
    }

    // combine the 4 groups (sl invariant under xor 8/16)
    #pragma unroll
    for (int j = 0; j < 4; j++) {
        #pragma unroll
        for (int off = 8; off <= 16; off <<= 1) {
            acc[j].x += __shfl_xor_sync(0xffffffffu, acc[j].x, off);
            acc[j].y += __shfl_xor_sync(0xffffffffu, acc[j].y, off);
        }
    }

    if (grp == 0) {
        const float4* b4 = (const float4*)b;
        float slope = a[0];
        float4* o4 = (float4*)(out + d * F);
        #pragma unroll
        for (int half4 = 0; half4 < 2; half4++) {
            float4 bb = b4[sl * 2 + half4];
            float2 a0 = acc[half4 * 2 + 0];
            float2 a1 = acc[half4 * 2 + 1];
            float4 r;
            r.x = a0.x * dd + bb.x;
            r.y = a0.y * dd + bb.y;
            r.z = a1.x * dd + bb.z;
            r.w = a1.y * dd + bb.w;
            r.x = (r.x >= 0.f) ? r.x : slope * r.x;
            r.y = (r.y >= 0.f) ? r.y : slope * r.y;
            r.z = (r.z >= 0.f) ? r.z : slope * r.z;
            r.w = (r.w >= 0.f) ? r.w : slope * r.w;
            o4[sl * 2 + half4] = r;
        }
    }
}

extern "C" void kernel_launch(void* const* d_in, const int* in_sizes, int n_in,
                              void* d_out, int out_size) {
    const float* x  = (const float*)d_in[0];
    const int*   ei = (const int*)d_in[1];   // edge_index [2, E] (int32)
    const float* W  = (const float*)d_in[2];
    const float* b  = (const float*)d_in[3];
    const float* a  = (const float*)d_in[4];
    float* out = (float*)d_out;

    k_count<<<(N_EDGES / 4 + 255) / 256, 256>>>(ei);
    k_scan_block<<<NB, SCAN_BLK>>>();
    k_finalize<<<NB, SCAN_BLK>>>();
    k_gemm<<<N_NODES / ROWS_BLK, 256>>>(x, W);     // needs g_dinv (after finalize)
    k_fill<<<(N_EDGES / 4 + 255) / 256, 256>>>(ei);
    k_accum<<<(N_NODES * 32 + 255) / 256, 256>>>(out, b, a);
}

// round 13
// speedup vs baseline: 1.1296x; 1.0929x over previous
#include <cuda_runtime.h>
#include <cuda_fp16.h>

#define N_NODES 100000
#define N_EDGES 1600000
#define F 64
#define SCAN_BLK 512
#define NB ((N_NODES + SCAN_BLK - 1) / SCAN_BLK)   // 196

// Scratch (device globals — zero-initialized at load; no allocation in kernel_launch)
__device__ int    g_cnt[N_NODES];        // zeroed by k_finalize after each use
__device__ int    g_scan[N_NODES];
__device__ int    g_bsum[NB];
__device__ int    g_rowptr[N_NODES + 1];
__device__ int    g_cursor[N_NODES];
__device__ int    g_src[N_EDGES];        // src indices bucketed by dst
__device__ float  g_dinv[N_NODES];
__device__ __half g_xsh[N_NODES * F];    // (x @ W) * dinv[row], fp16

// count in-degree (real edges only); 4 edges/thread via int4
__global__ void k_count(const int* __restrict__ ei) {
    int t = blockIdx.x * blockDim.x + threadIdx.x;
    if (t < N_EDGES / 4) {
        int4 d4 = ((const int4*)(ei + N_EDGES))[t];
        if ((unsigned)d4.x < N_NODES) atomicAdd(&g_cnt[d4.x], 1);
        if ((unsigned)d4.y < N_NODES) atomicAdd(&g_cnt[d4.y], 1);
        if ((unsigned)d4.z < N_NODES) atomicAdd(&g_cnt[d4.z], 1);
        if ((unsigned)d4.w < N_NODES) atomicAdd(&g_cnt[d4.w], 1);
    }
}

// per-block inclusive scan of g_cnt
__global__ void __launch_bounds__(SCAN_BLK) k_scan_block() {
    __shared__ int s[SCAN_BLK];
    int t = threadIdx.x;
    int i = blockIdx.x * SCAN_BLK + t;
    s[t] = (i < N_NODES) ? g_cnt[i] : 0;
    __syncthreads();
    #pragma unroll
    for (int off = 1; off < SCAN_BLK; off <<= 1) {
        int v = (t >= off) ? s[t - off] : 0;
        __syncthreads();
        s[t] += v;
        __syncthreads();
    }
    if (i < N_NODES) g_scan[i] = s[t];
    if (t == SCAN_BLK - 1) g_bsum[blockIdx.x] = s[t];
}

// finalize: per-block cross-block prefix from g_bsum (warp-reduced),
// then rowptr/cursor/dinv; resets g_cnt for the next graph replay.
__global__ void __launch_bounds__(SCAN_BLK) k_finalize() {
    __shared__ int base_sh;
    int b = blockIdx.x;
    int t = threadIdx.x;
    if (t < 32) {
        int s = 0;
        for (int j = t; j < b; j += 32) s += g_bsum[j];
        #pragma unroll
        for (int o = 16; o; o >>= 1) s += __shfl_xor_sync(0xffffffffu, s, o);
        if (t == 0) base_sh = s;
    }
    __syncthreads();
    int i = b * SCAN_BLK + t;
    if (i < N_NODES) {
        int incl = g_scan[i] + base_sh;
        int cnt = g_cnt[i];
        g_cnt[i] = 0;                              // restore invariant for replay
        int excl = incl - cnt;
        g_rowptr[i] = excl;
        g_cursor[i] = excl;
        if (i == N_NODES - 1) g_rowptr[N_NODES] = incl;
        g_dinv[i] = rsqrtf((float)(cnt + 1));      // +1 self-loop
    }
}

// bucket src indices by dst; 4 edges/thread, int-only stores (no gathers)
__global__ void k_fill(const int* __restrict__ ei) {
    int t = blockIdx.x * blockDim.x + threadIdx.x;
    if (t < N_EDGES / 4) {
        int4 s4 = ((const int4*)ei)[t];
        int4 d4 = ((const int4*)(ei + N_EDGES))[t];
        if ((unsigned)s4.x < N_NODES && (unsigned)d4.x < N_NODES)
            g_src[atomicAdd(&g_cursor[d4.x], 1)] = s4.x;
        if ((unsigned)s4.y < N_NODES && (unsigned)d4.y < N_NODES)
            g_src[atomicAdd(&g_cursor[d4.y], 1)] = s4.y;
        if ((unsigned)s4.z < N_NODES && (unsigned)d4.z < N_NODES)
            g_src[atomicAdd(&g_cursor[d4.z], 1)] = s4.z;
        if ((unsigned)s4.w < N_NODES && (unsigned)d4.w < N_NODES)
            g_src[atomicAdd(&g_cursor[d4.w], 1)] = s4.w;
    }
}

// GEMM (R9 known-good form): one col/thread, W column in 64 registers loaded
// once, x rows via broadcast LDS.128, fully unrolled. Epilogue folds dinv[row].
#define ROWS_BLK 32
__global__ void __launch_bounds__(256) k_gemm(const float* __restrict__ x,
                                              const float* __restrict__ W) {
    __shared__ float4 xsh[ROWS_BLK * 16];
    int tid = threadIdx.x;
    int c  = tid & 63;
    int rg = tid >> 6;

    float Wc[F];
    #pragma unroll
    for (int k = 0; k < F; k++) Wc[k] = W[k * F + c];

    int row0 = blockIdx.x * ROWS_BLK;
    const float4* x4 = (const float4*)(x + row0 * F);
    #pragma unroll
    for (int i = tid; i < ROWS_BLK * 16; i += 256) xsh[i] = x4[i];
    __syncthreads();

    #pragma unroll
    for (int rr = 0; rr < 8; rr++) {
        int r = rg * 8 + rr;
        float acc = 0.0f;
        #pragma unroll
        for (int k0 = 0; k0 < 16; k0++) {
            float4 xv = xsh[r * 16 + k0];       // broadcast within warp
            acc += xv.x * Wc[4 * k0 + 0];
            acc += xv.y * Wc[4 * k0 + 1];
            acc += xv.z * Wc[4 * k0 + 2];
            acc += xv.w * Wc[4 * k0 + 3];
        }
        int row = row0 + r;
        g_xsh[row * F + c] = __float2half_rn(acc * g_dinv[row]);
    }
}

// One warp per dst: 8 lanes/edge, 4 edges/warp-step, unit edge weight.
// Per 4 edges: 4 broadcast LDG.32 (src) + 4 LDG.128 gathers. Butterfly at end.
__global__ void __launch_bounds__(256) k_accum(float* __restrict__ out,
                                               const float* __restrict__ b,
                                               const float* __restrict__ a) {
    int d = (blockIdx.x * blockDim.x + threadIdx.x) >> 5;
    int lane = threadIdx.x & 31;
    if (d >= N_NODES) return;
    int beg = g_rowptr[d];
    int end = g_rowptr[d + 1];
    float dd = g_dinv[d];
    int sl  = lane & 7;     // 16B slice of the row (8 cols)
    int grp = lane >> 3;    // 0..3: which edge of the 4-edge step

    const float4* xs4 = (const float4*)g_xsh;   // row = 8 float4 (128 B)
    float2 acc[4] = {{0.f,0.f},{0.f,0.f},{0.f,0.f},{0.f,0.f}};

    // self-loop (group 0 only, so butterfly counts it once)
    if (grp == 0) {
        float4 hv = xs4[d * 8 + sl];
        const __half2* h = (const __half2*)&hv;
        #pragma unroll
        for (int j = 0; j < 4; j++) {
            float2 v = __half22float2(h[j]);
            acc[j].x += v.x; acc[j].y += v.y;
        }
    }

    #pragma unroll 2
    for (int i = beg + grp; i < end; i += 4) {
        int s = __ldg(g_src + i);               // uniform within the 8-lane group
        float4 hv = __ldg(xs4 + s * 8 + sl);
        const __half2* h = (const __half2*)&hv;
        #pragma unroll
        for (int j = 0; j < 4; j++) {
            float2 v = __half22float2(h[j]);
            acc[j].x += v.x; acc[j].y += v.y;
        }
    }

    // combine the 4 groups (sl invariant under xor 8/16)
    #pragma unroll
    for (int j = 0; j < 4; j++) {
        #pragma unroll
        for (int off = 8; off <= 16; off <<= 1) {
            acc[j].x += __shfl_xor_sync(0xffffffffu, acc[j].x, off);
            acc[j].y += __shfl_xor_sync(0xffffffffu, acc[j].y, off);
        }
    }

    if (grp == 0) {
        const float4* b4 = (const float4*)b;
        float slope = a[0];
        float4* o4 = (float4*)(out + d * F);
        #pragma unroll
        for (int half4 = 0; half4 < 2; half4++) {
            float4 bb = b4[sl * 2 + half4];
            float2 a0 = acc[half4 * 2 + 0];
            float2 a1 = acc[half4 * 2 + 1];
            float4 r;
            r.x = a0.x * dd + bb.x;
            r.y = a0.y * dd + bb.y;
            r.z = a1.x * dd + bb.z;
            r.w = a1.y * dd + bb.w;
            r.x = (r.x >= 0.f) ? r.x : slope * r.x;
            r.y = (r.y >= 0.f) ? r.y : slope * r.y;
            r.z = (r.z >= 0.f) ? r.z : slope * r.z;
            r.w = (r.w >= 0.f) ? r.w : slope * r.w;
            o4[sl * 2 + half4] = r;
        }
    }
}

extern "C" void kernel_launch(void* const* d_in, const int* in_sizes, int n_in,
                              void* d_out, int out_size) {
    const float* x  = (const float*)d_in[0];
    const int*   ei = (const int*)d_in[1];   // edge_index [2, E] (int32)
    const float* W  = (const float*)d_in[2];
    const float* b  = (const float*)d_in[3];
    const float* a  = (const float*)d_in[4];
    float* out = (float*)d_out;

    k_count<<<(N_EDGES / 4 + 255) / 256, 256>>>(ei);
    k_scan_block<<<NB, SCAN_BLK>>>();
    k_finalize<<<NB, SCAN_BLK>>>();
    k_gemm<<<N_NODES / ROWS_BLK, 256>>>(x, W);     // needs g_dinv (after finalize)
    k_fill<<<(N_EDGES / 4 + 255) / 256, 256>>>(ei);
    k_accum<<<(N_NODES * 32 + 255) / 256, 256>>>(out, b, a);
}

// round 14
// speedup vs baseline: 1.4186x; 1.2558x over previous
#include <cuda_runtime.h>
#include <cuda_fp16.h>
#include <cstdint>

#define N_NODES 100000
#define N_EDGES 1600000
#define F 64
#define SCAN_BLK 512
#define NB ((N_NODES + SCAN_BLK - 1) / SCAN_BLK)   // 196

// Scratch (device globals — zero-initialized at load; no allocation in kernel_launch)
__device__ int    g_cnt[N_NODES];        // zeroed by k_finalize after each use
__device__ int    g_scan[N_NODES];
__device__ int    g_bsum[NB];
__device__ int    g_rowptr[N_NODES + 1];
__device__ int    g_cursor[N_NODES];
__device__ int    g_src[N_EDGES];        // src indices bucketed by dst
__device__ float  g_dinv[N_NODES];
__device__ __half g_xsh[N_NODES * F];    // (x @ W) * dinv[row], fp16

static __device__ __forceinline__ uint32_t s2u(const void* p) {
    return (uint32_t)__cvta_generic_to_shared(p);
}

// count in-degree (real edges only); 4 edges/thread via int4
__global__ void k_count(const int* __restrict__ ei) {
    int t = blockIdx.x * blockDim.x + threadIdx.x;
    if (t < N_EDGES / 4) {
        int4 d4 = ((const int4*)(ei + N_EDGES))[t];
        if ((unsigned)d4.x < N_NODES) atomicAdd(&g_cnt[d4.x], 1);
        if ((unsigned)d4.y < N_NODES) atomicAdd(&g_cnt[d4.y], 1);
        if ((unsigned)d4.z < N_NODES) atomicAdd(&g_cnt[d4.z], 1);
        if ((unsigned)d4.w < N_NODES) atomicAdd(&g_cnt[d4.w], 1);
    }
}

// per-block inclusive scan of g_cnt
__global__ void __launch_bounds__(SCAN_BLK) k_scan_block() {
    __shared__ int s[SCAN_BLK];
    int t = threadIdx.x;
    int i = blockIdx.x * SCAN_BLK + t;
    s[t] = (i < N_NODES) ? g_cnt[i] : 0;
    __syncthreads();
    #pragma unroll
    for (int off = 1; off < SCAN_BLK; off <<= 1) {
        int v = (t >= off) ? s[t - off] : 0;
        __syncthreads();
        s[t] += v;
        __syncthreads();
    }
    if (i < N_NODES) g_scan[i] = s[t];
    if (t == SCAN_BLK - 1) g_bsum[blockIdx.x] = s[t];
}

// finalize: per-block cross-block prefix from g_bsum (warp-reduced),
// then rowptr/cursor/dinv; resets g_cnt for the next graph replay.
__global__ void __launch_bounds__(SCAN_BLK) k_finalize() {
    __shared__ int base_sh;
    int b = blockIdx.x;
    int t = threadIdx.x;
    if (t < 32) {
        int s = 0;
        for (int j = t; j < b; j += 32) s += g_bsum[j];
        #pragma unroll
        for (int o = 16; o; o >>= 1) s += __shfl_xor_sync(0xffffffffu, s, o);
        if (t == 0) base_sh = s;
    }
    __syncthreads();
    int i = b * SCAN_BLK + t;
    if (i < N_NODES) {
        int incl = g_scan[i] + base_sh;
        int cnt = g_cnt[i];
        g_cnt[i] = 0;                              // restore invariant for replay
        int excl = incl - cnt;
        g_rowptr[i] = excl;
        g_cursor[i] = excl;
        if (i == N_NODES - 1) g_rowptr[N_NODES] = incl;
        g_dinv[i] = rsqrtf((float)(cnt + 1));      // +1 self-loop
    }
}

// bucket src indices by dst; 4 edges/thread, int-only stores (no gathers)
__global__ void k_fill(const int* __restrict__ ei) {
    int t = blockIdx.x * blockDim.x + threadIdx.x;
    if (t < N_EDGES / 4) {
        int4 s4 = ((const int4*)ei)[t];
        int4 d4 = ((const int4*)(ei + N_EDGES))[t];
        if ((unsigned)s4.x < N_NODES && (unsigned)d4.x < N_NODES)
            g_src[atomicAdd(&g_cursor[d4.x], 1)] = s4.x;
        if ((unsigned)s4.y < N_NODES && (unsigned)d4.y < N_NODES)
            g_src[atomicAdd(&g_cursor[d4.y], 1)] = s4.y;
        if ((unsigned)s4.z < N_NODES && (unsigned)d4.z < N_NODES)
            g_src[atomicAdd(&g_cursor[d4.z], 1)] = s4.z;
        if ((unsigned)s4.w < N_NODES && (unsigned)d4.w < N_NODES)
            g_src[atomicAdd(&g_cursor[d4.w], 1)] = s4.w;
    }
}

// Tensor-core GEMM: 128 rows/block, 8 warps x m16 tiles; fp16 inputs (smem,
// 144B row skew = conflict-free ldmatrix), fp32 accum; epilogue folds dinv.
#define GT_ROWS 128
#define XPAD 72   // halfs per row (64 + 8 skew)
__global__ void __launch_bounds__(256) k_gemm(const float* __restrict__ x,
                                              const float* __restrict__ W) {
    __shared__ __half xs[GT_ROWS * XPAD];
    __shared__ __half ws[64 * XPAD];
    int tid = threadIdx.x;
    int row0 = blockIdx.x * GT_ROWS;

    // W [64][64] fp32 -> ws fp16 (row-major, same layout)
    const float4* W4 = (const float4*)W;           // 1024 float4
    for (int i = tid; i < 1024; i += 256) {
        float4 v = W4[i];
        int k = i >> 4, n4 = (i & 15) << 2;
        __half2* p = (__half2*)&ws[k * XPAD + n4];
        p[0] = __floats2half2_rn(v.x, v.y);
        p[1] = __floats2half2_rn(v.z, v.w);
    }
    // x rows -> xs fp16 (zero-fill OOB rows)
    for (int i = tid; i < GT_ROWS * 16; i += 256) {
        int r = i >> 4, c4 = (i & 15) << 2;
        int grow = row0 + r;
        float4 v = make_float4(0.f, 0.f, 0.f, 0.f);
        if (grow < N_NODES) v = ((const float4*)(x + grow * F))[i & 15];
        __half2* p = (__half2*)&xs[r * XPAD + c4];
        p[0] = __floats2half2_rn(v.x, v.y);
        p[1] = __floats2half2_rn(v.z, v.w);
    }
    __syncthreads();

    int warp = tid >> 5, lane = tid & 31;
    int wrow = warp * 16;

    float acc[8][4];
    #pragma unroll
    for (int n = 0; n < 8; n++)
        #pragma unroll
        for (int j = 0; j < 4; j++) acc[n][j] = 0.f;

    // A ldmatrix address: lanes 0-15 rows, lanes 16-31 same rows at k+8
    uint32_t a_row = (uint32_t)(wrow + (lane & 15));
    uint32_t a_koff = (uint32_t)((lane >> 4) << 3);
    uint32_t xbase = s2u(xs);
    uint32_t wbase = s2u(ws);

    #pragma unroll
    for (int ks = 0; ks < 4; ks++) {
        uint32_t aaddr = xbase + (a_row * XPAD + (uint32_t)(ks * 16) + a_koff) * 2;
        uint32_t a0, a1, a2, a3;
        asm volatile("ldmatrix.sync.aligned.m8n8.x4.shared.b16 {%0,%1,%2,%3}, [%4];"
                     : "=r"(a0), "=r"(a1), "=r"(a2), "=r"(a3) : "r"(aaddr));
        uint32_t brow = wbase + ((uint32_t)(ks * 16 + (lane & 15)) * XPAD) * 2;
        #pragma unroll
        for (int nt = 0; nt < 8; nt++) {
            uint32_t baddr = brow + (uint32_t)(nt * 8) * 2;
            uint32_t b0, b1;
            asm volatile("ldmatrix.sync.aligned.m8n8.x2.trans.shared.b16 {%0,%1}, [%2];"
                         : "=r"(b0), "=r"(b1) : "r"(baddr));
            asm volatile("mma.sync.aligned.m16n8k16.row.col.f32.f16.f16.f32 "
                         "{%0,%1,%2,%3}, {%4,%5,%6,%7}, {%8,%9}, {%0,%1,%2,%3};"
                         : "+f"(acc[nt][0]), "+f"(acc[nt][1]),
                           "+f"(acc[nt][2]), "+f"(acc[nt][3])
                         : "r"(a0), "r"(a1), "r"(a2), "r"(a3), "r"(b0), "r"(b1));
        }
    }

    // epilogue: rows (mrow, mrow+8); scale by dinv and store half2
    int mrow = row0 + wrow + (lane >> 2);
    float d0 = (mrow     < N_NODES) ? g_dinv[mrow]     : 0.f;
    float d1 = (mrow + 8 < N_NODES) ? g_dinv[mrow + 8] : 0.f;
    __half2* o2 = (__half2*)g_xsh;
    int cslot = lane & 3;                       // half2 slot within n-tile
    #pragma unroll
    for (int nt = 0; nt < 8; nt++) {
        int h2 = nt * 4 + cslot;                // half2 index in the 64-col row
        if (mrow < N_NODES)
            o2[mrow * 32 + h2] = __floats2half2_rn(acc[nt][0] * d0, acc[nt][1] * d0);
        if (mrow + 8 < N_NODES)
            o2[(mrow + 8) * 32 + h2] = __floats2half2_rn(acc[nt][2] * d1, acc[nt][3] * d1);
    }
}

// One warp per dst: 8 lanes/edge, 4 edges/warp-step, unit edge weight.
__global__ void __launch_bounds__(256) k_accum(float* __restrict__ out,
                                               const float* __restrict__ b,
                                               const float* __restrict__ a) {
    int d = (blockIdx.x * blockDim.x + threadIdx.x) >> 5;
    int lane = threadIdx.x & 31;
    if (d >= N_NODES) return;
    int beg = g_rowptr[d];
    int end = g_rowptr[d + 1];
    float dd = g_dinv[d];
    int sl  = lane & 7;     // 16B slice of the row (8 cols)
    int grp = lane >> 3;    // 0..3: which edge of the 4-edge step

    const float4* xs4 = (const float4*)g_xsh;   // row = 8 float4 (128 B)
    float2 acc[4] = {{0.f,0.f},{0.f,0.f},{0.f,0.f},{0.f,0.f}};

    if (grp == 0) {                              // self-loop, counted once
        float4 hv = xs4[d * 8 + sl];
        const __half2* h = (const __half2*)&hv;
        #pragma unroll
        for (int j = 0; j < 4; j++) {
            float2 v = __half22float2(h[j]);
            acc[j].x += v.x; acc[j].y += v.y;
        }
    }

    #pragma unroll 2
    for (int i = beg + grp; i < end; i += 4) {
        int s = __ldg(g_src + i);               // uniform within the 8-lane group
        float4 hv = __ldg(xs4 + s * 8 + sl);
        const __half2* h = (const __half2*)&hv;
        #pragma unroll
        for (int j = 0; j < 4; j++) {
            float2 v = __half22float2(h[j]);
            acc[j].x += v.x; acc[j].y += v.y;
        }
    }

    #pragma unroll
    for (int j = 0; j < 4; j++) {
        #pragma unroll
        for (int off = 8; off <= 16; off <<= 1) {
            acc[j].x += __shfl_xor_sync(0xffffffffu, acc[j].x, off);
            acc[j].y += __shfl_xor_sync(0xffffffffu, acc[j].y, off);
        }
    }

    if (grp == 0) {
        const float4* b4 = (const float4*)b;
        float slope = a[0];
        float4* o4 = (float4*)(out + d * F);
        #pragma unroll
        for (int half4 = 0; half4 < 2; half4++) {
            float4 bb = b4[sl * 2 + half4];
            float2 a0 = acc[half4 * 2 + 0];
            float2 a1 = acc[half4 * 2 + 1];
            float4 r;
            r.x = a0.x * dd + bb.x;
            r.y = a0.y * dd + bb.y;
            r.z = a1.x * dd + bb.z;
            r.w = a1.y * dd + bb.w;
            r.x = (r.x >= 0.f) ? r.x : slope * r.x;
            r.y = (r.y >= 0.f) ? r.y : slope * r.y;
            r.z = (r.z >= 0.f) ? r.z : slope * r.z;
            r.w = (r.w >= 0.f) ? r.w : slope * r.w;
            o4[sl * 2 + half4] = r;
        }
    }
}

extern "C" void kernel_launch(void* const* d_in, const int* in_sizes, int n_in,
                              void* d_out, int out_size) {
    const float* x  = (const float*)d_in[0];
    const int*   ei = (const int*)d_in[1];   // edge_index [2, E] (int32)
    const float* W  = (const float*)d_in[2];
    const float* b  = (const float*)d_in[3];
    const float* a  = (const float*)d_in[4];
    float* out = (float*)d_out;

    k_count<<<(N_EDGES / 4 + 255) / 256, 256>>>(ei);
    k_scan_block<<<NB, SCAN_BLK>>>();
    k_finalize<<<NB, SCAN_BLK>>>();
    k_gemm<<<(N_NODES + GT_ROWS - 1) / GT_ROWS, 256>>>(x, W);  // needs g_dinv
    k_fill<<<(N_EDGES / 4 + 255) / 256, 256>>>(ei);
    k_accum<<<(N_NODES * 32 + 255) / 256, 256>>>(out, b, a);
}

// round 16
// speedup vs baseline: 1.4518x; 1.0234x over previous
#include <cuda_runtime.h>
#include <cuda_fp16.h>
#include <cstdint>

#define N_NODES 100000
#define N_EDGES 1600000
#define F 64
#define SCAN_BLK 512
#define NB ((N_NODES + SCAN_BLK - 1) / SCAN_BLK)   // 196

// Scratch (device globals — zero-initialized at load; no allocation in kernel_launch)
__device__ int    g_cnt[N_NODES];        // zeroed by k_finalize after each use
__device__ int    g_scan[N_NODES];
__device__ int    g_bsum[NB];
__device__ int    g_rowptr[N_NODES + 1];
__device__ int    g_cursor[N_NODES];
__device__ int    g_src[N_EDGES];        // src indices bucketed by dst
__device__ float  g_dinv[N_NODES];
__device__ __half g_xsh[N_NODES * F];    // (x @ W) * dinv[row], fp16

static __device__ __forceinline__ uint32_t s2u(const void* p) {
    return (uint32_t)__cvta_generic_to_shared(p);
}
static __device__ __forceinline__ uint32_t h2_bits(__half2 h) {
    return *reinterpret_cast<uint32_t*>(&h);
}

// count in-degree (real edges only); 4 edges/thread via int4
__global__ void k_count(const int* __restrict__ ei) {
    int t = blockIdx.x * blockDim.x + threadIdx.x;
    if (t < N_EDGES / 4) {
        int4 d4 = ((const int4*)(ei + N_EDGES))[t];
        if ((unsigned)d4.x < N_NODES) atomicAdd(&g_cnt[d4.x], 1);
        if ((unsigned)d4.y < N_NODES) atomicAdd(&g_cnt[d4.y], 1);
        if ((unsigned)d4.z < N_NODES) atomicAdd(&g_cnt[d4.z], 1);
        if ((unsigned)d4.w < N_NODES) atomicAdd(&g_cnt[d4.w], 1);
    }
}

// per-block inclusive scan of g_cnt — warp-shuffle version (2 barriers)
__global__ void __launch_bounds__(SCAN_BLK) k_scan_block() {
    __shared__ int wsum[16];
    int t = threadIdx.x;
    int lane = t & 31, warp = t >> 5;
    int i = blockIdx.x * SCAN_BLK + t;
    int v = (i < N_NODES) ? g_cnt[i] : 0;
    #pragma unroll
    for (int off = 1; off < 32; off <<= 1) {
        int u = __shfl_up_sync(0xffffffffu, v, off);
        if (lane >= off) v += u;
    }
    if (lane == 31) wsum[warp] = v;
    __syncthreads();
    if (t < 16) {
        int s = wsum[t];
        #pragma unroll
        for (int off = 1; off < 16; off <<= 1) {
            int u = __shfl_up_sync(0x0000ffffu, s, off, 16);
            if (t >= off) s += u;
        }
        wsum[t] = s;
    }
    __syncthreads();
    if (warp > 0) v += wsum[warp - 1];
    if (i < N_NODES) g_scan[i] = v;
    if (t == SCAN_BLK - 1) g_bsum[blockIdx.x] = v;
}

// finalize: per-block cross-block prefix from g_bsum (warp-reduced),
// then rowptr/cursor/dinv; resets g_cnt for the next graph replay.
__global__ void __launch_bounds__(SCAN_BLK) k_finalize() {
    __shared__ int base_sh;
    int b = blockIdx.x;
    int t = threadIdx.x;
    if (t < 32) {
        int s = 0;
        for (int j = t; j < b; j += 32) s += g_bsum[j];
        #pragma unroll
        for (int o = 16; o; o >>= 1) s += __shfl_xor_sync(0xffffffffu, s, o);
        if (t == 0) base_sh = s;
    }
    __syncthreads();
    int i = b * SCAN_BLK + t;
    if (i < N_NODES) {
        int incl = g_scan[i] + base_sh;
        int cnt = g_cnt[i];
        g_cnt[i] = 0;                              // restore invariant for replay
        int excl = incl - cnt;
        g_rowptr[i] = excl;
        g_cursor[i] = excl;
        if (i == N_NODES - 1) g_rowptr[N_NODES] = incl;
        g_dinv[i] = rsqrtf((float)(cnt + 1));      // +1 self-loop
    }
}

// bucket src indices by dst; 4 edges/thread, int-only stores (no gathers)
__global__ void k_fill(const int* __restrict__ ei) {
    int t = blockIdx.x * blockDim.x + threadIdx.x;
    if (t < N_EDGES / 4) {
        int4 s4 = ((const int4*)ei)[t];
        int4 d4 = ((const int4*)(ei + N_EDGES))[t];
        if ((unsigned)s4.x < N_NODES && (unsigned)d4.x < N_NODES)
            g_src[atomicAdd(&g_cursor[d4.x], 1)] = s4.x;
        if ((unsigned)s4.y < N_NODES && (unsigned)d4.y < N_NODES)
            g_src[atomicAdd(&g_cursor[d4.y], 1)] = s4.y;
        if ((unsigned)s4.z < N_NODES && (unsigned)d4.z < N_NODES)
            g_src[atomicAdd(&g_cursor[d4.z], 1)] = s4.z;
        if ((unsigned)s4.w < N_NODES && (unsigned)d4.w < N_NODES)
            g_src[atomicAdd(&g_cursor[d4.w], 1)] = s4.w;
    }
}

// Tensor-core GEMM v3: x staged fp32 via cp.async (high MLP, no reg landing),
// A fragments built by direct LDS.64 + cvt; B (W) fp16 smem + ldmatrix.trans.
#define GT_ROWS 128
#define XS32 68   // fp32 stage row stride (floats): 272B = 17x16B, bank-staggered
#define XPAD 72   // fp16 W row stride (halfs)
__global__ void __launch_bounds__(256) k_gemm(const float* __restrict__ x,
                                              const float* __restrict__ W) {
    __shared__ float  xs32[GT_ROWS * XS32];
    __shared__ __half ws[64 * XPAD];
    int tid = threadIdx.x;
    int row0 = blockIdx.x * GT_ROWS;

    // x rows -> fp32 smem via cp.async (8 x 16B per thread); zero OOB rows
    for (int i = tid; i < GT_ROWS * 16; i += 256) {
        int r = i >> 4, c4 = (i & 15) * 4;
        int grow = row0 + r;
        float* dst = &xs32[r * XS32 + c4];
        if (grow < N_NODES) {
            const float* src = x + grow * F + c4;
            asm volatile("cp.async.cg.shared.global [%0], [%1], 16;"
                         :: "r"(s2u(dst)), "l"(src));
        } else {
            *(float4*)dst = make_float4(0.f, 0.f, 0.f, 0.f);
        }
    }
    asm volatile("cp.async.commit_group;");

    // W [64][64] fp32 -> ws fp16 (row-major, same layout)
    const float4* W4 = (const float4*)W;           // 1024 float4
    for (int i = tid; i < 1024; i += 256) {
        float4 v = W4[i];
        int k = i >> 4, n4 = (i & 15) << 2;
        __half2* p = (__half2*)&ws[k * XPAD + n4];
        p[0] = __floats2half2_rn(v.x, v.y);
        p[1] = __floats2half2_rn(v.z, v.w);
    }
    asm volatile("cp.async.wait_group 0;");
    __syncthreads();

    int warp = tid >> 5, lane = tid & 31;
    int wrow = warp * 16;
    int qr = lane >> 2, qc = (lane & 3) * 2;

    float acc[8][4];
    #pragma unroll
    for (int n = 0; n < 8; n++)
        #pragma unroll
        for (int j = 0; j < 4; j++) acc[n][j] = 0.f;

    uint32_t wbase = s2u(ws);

    #pragma unroll
    for (int ks = 0; ks < 4; ks++) {
        // A fragments directly from fp32 stage: {m0k0, m8k0, m0k8, m8k8}
        const float* abase = &xs32[(wrow + qr) * XS32 + ks * 16 + qc];
        float2 f0 = *(const float2*)(abase);
        float2 f1 = *(const float2*)(abase + 8 * XS32);
        float2 f2 = *(const float2*)(abase + 8);
        float2 f3 = *(const float2*)(abase + 8 * XS32 + 8);
        uint32_t a0 = h2_bits(__floats2half2_rn(f0.x, f0.y));
        uint32_t a1 = h2_bits(__floats2half2_rn(f1.x, f1.y));
        uint32_t a2 = h2_bits(__floats2half2_rn(f2.x, f2.y));
        uint32_t a3 = h2_bits(__floats2half2_rn(f3.x, f3.y));

        uint32_t brow = wbase + ((uint32_t)(ks * 16 + (lane & 15)) * XPAD) * 2;
        #pragma unroll
        for (int nt = 0; nt < 8; nt++) {
            uint32_t baddr = brow + (uint32_t)(nt * 8) * 2;
            uint32_t b0, b1;
            asm volatile("ldmatrix.sync.aligned.m8n8.x2.trans.shared.b16 {%0,%1}, [%2];"
                         : "=r"(b0), "=r"(b1) : "r"(baddr));
            asm volatile("mma.sync.aligned.m16n8k16.row.col.f32.f16.f16.f32 "
                         "{%0,%1,%2,%3}, {%4,%5,%6,%7}, {%8,%9}, {%0,%1,%2,%3};"
                         : "+f"(acc[nt][0]), "+f"(acc[nt][1]),
                           "+f"(acc[nt][2]), "+f"(acc[nt][3])
                         : "r"(a0), "r"(a1), "r"(a2), "r"(a3), "r"(b0), "r"(b1));
        }
    }

    // epilogue: rows (mrow, mrow+8); scale by dinv and store half2
    int mrow = row0 + wrow + qr;
    float d0 = (mrow     < N_NODES) ? g_dinv[mrow]     : 0.f;
    float d1 = (mrow + 8 < N_NODES) ? g_dinv[mrow + 8] : 0.f;
    __half2* o2 = (__half2*)g_xsh;
    int cslot = lane & 3;
    #pragma unroll
    for (int nt = 0; nt < 8; nt++) {
        int h2 = nt * 4 + cslot;
        if (mrow < N_NODES)
            o2[mrow * 32 + h2] = __floats2half2_rn(acc[nt][0] * d0, acc[nt][1] * d0);
        if (mrow + 8 < N_NODES)
            o2[(mrow + 8) * 32 + h2] = __floats2half2_rn(acc[nt][2] * d1, acc[nt][3] * d1);
    }
}

// One warp per dst: 8 lanes/edge, 4 edges/warp-step, unit edge weight.
__global__ void __launch_bounds__(256) k_accum(float* __restrict__ out,
                                               const float* __restrict__ b,
                                               const float* __restrict__ a) {
    int d = (blockIdx.x * blockDim.x + threadIdx.x) >> 5;
    int lane = threadIdx.x & 31;
    if (d >= N_NODES) return;
    int beg = g_rowptr[d];
    int end = g_rowptr[d + 1];
    float dd = g_dinv[d];
    int sl  = lane & 7;     // 16B slice of the row (8 cols)
    int grp = lane >> 3;    // 0..3: which edge of the 4-edge step

    const float4* xs4 = (const float4*)g_xsh;   // row = 8 float4 (128 B)
    float2 acc[4] = {{0.f,0.f},{0.f,0.f},{0.f,0.f},{0.f,0.f}};

    if (grp == 0) {                              // self-loop, counted once
        float4 hv = xs4[d * 8 + sl];
        const __half2* h = (const __half2*)&hv;
        #pragma unroll
        for (int j = 0; j < 4; j++) {
            float2 v = __half22float2(h[j]);
            acc[j].x += v.x; acc[j].y += v.y;
        }
    }

    #pragma unroll 2
    for (int i = beg + grp; i < end; i += 4) {
        int s = __ldg(g_src + i);               // uniform within the 8-lane group
        float4 hv = __ldg(xs4 + s * 8 + sl);
        const __half2* h = (const __half2*)&hv;
        #pragma unroll
        for (int j = 0; j < 4; j++) {
            float2 v = __half22float2(h[j]);
            acc[j].x += v.x; acc[j].y += v.y;
        }
    }

    #pragma unroll
    for (int j = 0; j < 4; j++) {
        #pragma unroll
        for (int off = 8; off <= 16; off <<= 1) {
            acc[j].x += __shfl_xor_sync(0xffffffffu, acc[j].x, off);
            acc[j].y += __shfl_xor_sync(0xffffffffu, acc[j].y, off);
        }
    }

    if (grp == 0) {
        const float4* b4 = (const float4*)b;
        float slope = a[0];
        float4* o4 = (float4*)(out + d * F);
        #pragma unroll
        for (int half4 = 0; half4 < 2; half4++) {
            float4 bb = b4[sl * 2 + half4];
            float2 a0 = acc[half4 * 2 + 0];
            float2 a1 = acc[half4 * 2 + 1];
            float4 r;
            r.x = a0.x * dd + bb.x;
            r.y = a0.y * dd + bb.y;
            r.z = a1.x * dd + bb.z;
            r.w = a1.y * dd + bb.w;
            r.x = (r.x >= 0.f) ? r.x : slope * r.x;
            r.y = (r.y >= 0.f) ? r.y : slope * r.y;
            r.z = (r.z >= 0.f) ? r.z : slope * r.z;
            r.w = (r.w >= 0.f) ? r.w : slope * r.w;
            o4[sl * 2 + half4] = r;
        }
    }
}

extern "C" void kernel_launch(void* const* d_in, const int* in_sizes, int n_in,
                              void* d_out, int out_size) {
    const float* x  = (const float*)d_in[0];
    const int*   ei = (const int*)d_in[1];   // edge_index [2, E] (int32)
    const float* W  = (const float*)d_in[2];
    const float* b  = (const float*)d_in[3];
    const float* a  = (const float*)d_in[4];
    float* out = (float*)d_out;

    k_count<<<(N_EDGES / 4 + 255) / 256, 256>>>(ei);
    k_scan_block<<<NB, SCAN_BLK>>>();
    k_finalize<<<NB, SCAN_BLK>>>();
    k_gemm<<<(N_NODES + GT_ROWS - 1) / GT_ROWS, 256>>>(x, W);  // needs g_dinv
    k_fill<<<(N_EDGES / 4 + 255) / 256, 256>>>(ei);
    k_accum<<<(N_NODES * 32 + 255) / 256, 256>>>(out, b, a);
}